// round 2
// baseline (speedup 1.0000x reference)
#include <cuda_runtime.h>
#include <cuda_bf16.h>
#include <math.h>

#define NN 160
#define EE 256
#define HH 4
#define DD 64
#define ROWS (NN*NN)          // 25600
#define PC 784                // packed projection cols
#define KP 68                 // smem K/V pitch (floats)
#define SCALE 0.125f
#define LN_EPS 1e-5f

// column offsets in packed projection
#define C_QIN   0
#define C_KIN   256
#define C_VIN   320
#define C_EGIN  384
#define C_QOUT  392
#define C_KOUT  648
#define C_VOUT  712
#define C_EGOUT 776

// -------------------- scratch (static device globals; no runtime alloc) ----
__device__ float g_eln[ROWS * EE];     // 26.2 MB
__device__ float g_proj[ROWS * PC];    // 80.3 MB
__device__ float g_va[ROWS * 512];     // 52.4 MB
__device__ float g_wcat[EE * PC];      // 0.8 MB
__device__ float g_bcat[PC];

// -------------------- block reduce helper (256 threads) --------------------
__device__ __forceinline__ float block_sum256(float v) {
    __shared__ float red[8];
    __shared__ float tot;
    #pragma unroll
    for (int o = 16; o; o >>= 1) v += __shfl_xor_sync(~0u, v, o);
    int wid = threadIdx.x >> 5, lane = threadIdx.x & 31;
    if (lane == 0) red[wid] = v;
    __syncthreads();
    float s = (lane < 8) ? red[lane] : 0.f;
    #pragma unroll
    for (int o = 4; o; o >>= 1) s += __shfl_xor_sync(~0u, s, o);
    if (threadIdx.x == 0) tot = s;
    __syncthreads();
    return tot;
}

// -------------------- LayerNorm ---------------------------------------------
__global__ void ln_kernel(const float* __restrict__ e,
                          const float* __restrict__ g,
                          const float* __restrict__ b) {
    int r = blockIdx.x;
    int c = threadIdx.x;
    float x = e[(size_t)r * EE + c];
    float mu = block_sum256(x) * (1.f / EE);
    float dx = x - mu;
    float var = block_sum256(dx * dx) * (1.f / EE);
    g_eln[(size_t)r * EE + c] = dx * rsqrtf(var + LN_EPS) * g[c] + b[c];
}

// -------------------- pack weights (fold SCALE into Q) ----------------------
__global__ void pack_kernel(const float* __restrict__ Wq_in,  const float* __restrict__ bq_in,
                            const float* __restrict__ Wkv_in, const float* __restrict__ bkv_in,
                            const float* __restrict__ Weg_in, const float* __restrict__ beg_in,
                            const float* __restrict__ Wq_out, const float* __restrict__ bq_out,
                            const float* __restrict__ Wkv_out,const float* __restrict__ bkv_out,
                            const float* __restrict__ Weg_out,const float* __restrict__ beg_out) {
    int k = blockIdx.x; // 0..255
    for (int c = threadIdx.x; c < PC; c += blockDim.x) {
        float w, bb;
        if (c < 256)      { w = Wq_in [k*256 +  c      ]*SCALE; bb = bq_in [c      ]*SCALE; }
        else if (c < 384) { w = Wkv_in[k*128 + (c-256) ];       bb = bkv_in[c-256  ]; }
        else if (c < 392) { w = Weg_in[k*8   + (c-384) ];       bb = beg_in[c-384  ]; }
        else if (c < 648) { w = Wq_out[k*256 + (c-392) ]*SCALE; bb = bq_out[c-392  ]*SCALE; }
        else if (c < 776) { w = Wkv_out[k*128+ (c-648) ];       bb = bkv_out[c-648 ]; }
        else              { w = Weg_out[k*8  + (c-776) ];       bb = beg_out[c-776 ]; }
        g_wcat[k*PC + c] = w;
        if (k == 0) g_bcat[c] = bb;
    }
}

// -------------------- SGEMM 128x64x16, 256 threads, 8x4 microtile -----------
__global__ __launch_bounds__(256)
void sgemm_bias(const float* __restrict__ A, const float* __restrict__ B,
                const float* __restrict__ bias, float* __restrict__ C,
                int M, int N, int K) {
    const int BM = 128, BN = 64, BK = 16;
    __shared__ float As[BK][BM + 4];
    __shared__ float Bs[BK][BN + 4];
    int tid = threadIdx.x;
    int tr = tid >> 4;      // 0..15
    int tc = tid & 15;      // 0..15
    int bm = blockIdx.y * BM;
    int bn = blockIdx.x * BN;
    float acc[8][4];
    #pragma unroll
    for (int m = 0; m < 8; m++)
        #pragma unroll
        for (int n = 0; n < 4; n++) acc[m][n] = 0.f;

    for (int k0 = 0; k0 < K; k0 += BK) {
        #pragma unroll
        for (int l = 0; l < 2; l++) {
            int i = tid * 2 + l;               // 0..511
            int row = i >> 2;                  // 0..127
            int kq = (i & 3) * 4;              // 0,4,8,12
            float4 v = *(const float4*)(A + (size_t)(bm + row) * K + k0 + kq);
            As[kq + 0][row] = v.x; As[kq + 1][row] = v.y;
            As[kq + 2][row] = v.z; As[kq + 3][row] = v.w;
        }
        {
            int row = tid >> 4;                // 0..15
            int cq = (tid & 15) * 4;           // 0..60
            float4 v = make_float4(0.f, 0.f, 0.f, 0.f);
            if (bn + cq < N)
                v = *(const float4*)(B + (size_t)(k0 + row) * N + bn + cq);
            *(float4*)&Bs[row][cq] = v;
        }
        __syncthreads();
        #pragma unroll
        for (int kk = 0; kk < BK; kk++) {
            float a[8], bv[4];
            float4 a0 = *(const float4*)&As[kk][tr * 8];
            float4 a1 = *(const float4*)&As[kk][tr * 8 + 4];
            a[0]=a0.x; a[1]=a0.y; a[2]=a0.z; a[3]=a0.w;
            a[4]=a1.x; a[5]=a1.y; a[6]=a1.z; a[7]=a1.w;
            float4 b0 = *(const float4*)&Bs[kk][tc * 4];
            bv[0]=b0.x; bv[1]=b0.y; bv[2]=b0.z; bv[3]=b0.w;
            #pragma unroll
            for (int m = 0; m < 8; m++)
                #pragma unroll
                for (int n = 0; n < 4; n++)
                    acc[m][n] += a[m] * bv[n];
        }
        __syncthreads();
    }
    #pragma unroll
    for (int m = 0; m < 8; m++) {
        int row = bm + tr * 8 + m;
        #pragma unroll
        for (int n = 0; n < 4; n++) {
            int col = bn + tc * 4 + n;
            if (col < N)
                C[(size_t)row * N + col] = acc[m][n] + bias[col];
        }
    }
}

// -------------------- fused triangle attention (one branch) -----------------
// in-branch (OUT=false): H[i,j,k,h] = sum_d Q[i,j,d,h] K[j,k,d] + EG[i,k,h] + mask[i,k]
//                        softmax over k; gate = sigmoid(EG[i,k,4+h]+mask[i,k])
//                        Va[i,j,d,h]  = sum_k A[k,h] V[j,k,d]        -> chan d*8+h
// out-branch (OUT=true): keys K[k*160+j], bias/gate EG[k,i], mask[k,i],
//                        V[k*160+j]                                  -> chan d*8+4+h
template<bool OUT>
__global__ __launch_bounds__(256)
void attn_kernel(const float* __restrict__ proj, const float* __restrict__ mask,
                 float* __restrict__ va) {
    extern __shared__ float sm[];
    float* Ksm = sm;                       // 160*68
    float* Vsm = Ksm + NN * KP;            // 160*68
    float* qsm = Vsm + NN * KP;            // 4*64 (q transposed: [h][d])
    float* lg  = qsm + 256;                // 640 : logits/probs [k*4+h]
    float* eg  = lg + 640;                 // 160*8
    float* msm = eg + NN * 8;              // 160

    const int j = blockIdx.x;
    const int ic = blockIdx.y;
    const int tid = threadIdx.x;
    const int KVBASE = OUT ? C_KOUT : C_KIN;
    const int QBASE  = OUT ? C_QOUT : C_QIN;
    const int EGBASE = OUT ? C_EGOUT : C_EGIN;

    // stage K/V tile for this j (shared across all 16 queries)
    for (int idx = tid; idx < NN * DD; idx += 256) {
        int k = idx >> 6, d = idx & 63;
        int row = OUT ? (k * NN + j) : (j * NN + k);
        const float* pr = proj + (size_t)row * PC + KVBASE;
        Ksm[k * KP + d] = pr[d];
        Vsm[k * KP + d] = pr[64 + d];
    }
    __syncthreads();

    for (int ii = 0; ii < 16; ii++) {
        int i = ic * 16 + ii;
        // stage q (transposed), eg row, mask row
        {
            int c = tid;
            qsm[(c & 3) * 64 + (c >> 2)] = proj[(size_t)(i * NN + j) * PC + QBASE + c];
        }
        for (int idx = tid; idx < NN * 8; idx += 256) {
            int k = idx >> 3, c2 = idx & 7;
            int row = OUT ? (k * NN + i) : (i * NN + k);
            eg[idx] = proj[(size_t)row * PC + EGBASE + c2];
        }
        if (tid < NN) {
            int k = tid;
            int row = OUT ? (k * NN + i) : (i * NN + k);
            msm[k] = mask[row];
        }
        __syncthreads();

        // logits
        for (int idx = tid; idx < NN * HH; idx += 256) {
            int h = idx & 3, k = idx >> 2;
            const float* kp = Ksm + k * KP;
            const float* qp = qsm + h * 64;
            float acc = 0.f;
            #pragma unroll
            for (int d = 0; d < 64; d += 4) {
                float4 kv = *(const float4*)(kp + d);
                float4 qv = *(const float4*)(qp + d);
                acc += kv.x * qv.x + kv.y * qv.y + kv.z * qv.z + kv.w * qv.w;
            }
            lg[k * 4 + h] = acc + eg[k * 8 + h] + msm[k];
        }
        __syncthreads();

        // softmax + gate, warp w handles head h=w
        {
            int wid = tid >> 5, lane = tid & 31;
            if (wid < HH) {
                int h = wid;
                float mx = -1e30f;
                for (int k = lane; k < NN; k += 32) mx = fmaxf(mx, lg[k * 4 + h]);
                #pragma unroll
                for (int o = 16; o; o >>= 1) mx = fmaxf(mx, __shfl_xor_sync(~0u, mx, o));
                float s = 0.f;
                for (int k = lane; k < NN; k += 32) {
                    float ev = __expf(lg[k * 4 + h] - mx);
                    lg[k * 4 + h] = ev;
                    s += ev;
                }
                #pragma unroll
                for (int o = 16; o; o >>= 1) s += __shfl_xor_sync(~0u, s, o);
                float rinv = 1.f / s;
                for (int k = lane; k < NN; k += 32) {
                    float gz = eg[k * 8 + 4 + h] + msm[k];
                    float gate = 1.f / (1.f + __expf(-gz));
                    lg[k * 4 + h] = lg[k * 4 + h] * rinv * gate;
                }
            }
        }
        __syncthreads();

        // A @ V
        {
            int h = tid & 3, d = tid >> 2;
            float acc = 0.f;
            #pragma unroll 8
            for (int k = 0; k < NN; k++)
                acc += lg[k * 4 + h] * Vsm[k * KP + d];
            va[(size_t)(i * NN + j) * 512 + d * 8 + (OUT ? 4 : 0) + h] = acc;
        }
        __syncthreads();
    }
}

// -------------------- launch -----------------------------------------------
extern "C" void kernel_launch(void* const* d_in, const int* in_sizes, int n_in,
                              void* d_out, int out_size) {
    const float* e       = (const float*)d_in[0];
    const float* mask    = (const float*)d_in[1];
    const float* ln_g    = (const float*)d_in[2];
    const float* ln_b    = (const float*)d_in[3];
    const float* Wq_in   = (const float*)d_in[4];
    const float* bq_in   = (const float*)d_in[5];
    const float* Wkv_in  = (const float*)d_in[6];
    const float* bkv_in  = (const float*)d_in[7];
    const float* Weg_in  = (const float*)d_in[8];
    const float* beg_in  = (const float*)d_in[9];
    const float* Wq_out  = (const float*)d_in[10];
    const float* bq_out  = (const float*)d_in[11];
    const float* Wkv_out = (const float*)d_in[12];
    const float* bkv_out = (const float*)d_in[13];
    const float* Weg_out = (const float*)d_in[14];
    const float* beg_out = (const float*)d_in[15];
    const float* Wo      = (const float*)d_in[16];
    const float* bo      = (const float*)d_in[17];
    float* out = (float*)d_out;

    float *p_eln, *p_proj, *p_va, *p_wcat, *p_bcat;
    cudaGetSymbolAddress((void**)&p_eln,  g_eln);
    cudaGetSymbolAddress((void**)&p_proj, g_proj);
    cudaGetSymbolAddress((void**)&p_va,   g_va);
    cudaGetSymbolAddress((void**)&p_wcat, g_wcat);
    cudaGetSymbolAddress((void**)&p_bcat, g_bcat);

    const int smem_attn = (NN * KP * 2 + 256 + 640 + NN * 8 + NN) * (int)sizeof(float);
    cudaFuncSetAttribute(attn_kernel<false>, cudaFuncAttributeMaxDynamicSharedMemorySize, smem_attn);
    cudaFuncSetAttribute(attn_kernel<true>,  cudaFuncAttributeMaxDynamicSharedMemorySize, smem_attn);

    // 1. LayerNorm
    ln_kernel<<<ROWS, 256>>>(e, ln_g, ln_b);
    // 2. pack weights
    pack_kernel<<<EE, 256>>>(Wq_in, bq_in, Wkv_in, bkv_in, Weg_in, beg_in,
                             Wq_out, bq_out, Wkv_out, bkv_out, Weg_out, beg_out);
    // 3. all projections in one GEMM: [25600,256] x [256,784]
    sgemm_bias<<<dim3((PC + 63) / 64, ROWS / 128), 256>>>(p_eln, p_wcat, p_bcat, p_proj,
                                                          ROWS, PC, EE);
    // 4+5. fused attention, both branches
    attn_kernel<false><<<dim3(NN, NN / 16), 256, smem_attn>>>(p_proj, mask, p_va);
    attn_kernel<true><<<dim3(NN, NN / 16), 256, smem_attn>>>(p_proj, mask, p_va);
    // 6. output projection: [25600,512] x [512,256] -> d_out
    sgemm_bias<<<dim3(256 / 64, ROWS / 128), 256>>>(p_va, Wo, bo, out,
                                                    ROWS, EE, 2 * EE);
}

// round 3
// speedup vs baseline: 2.3145x; 2.3145x over previous
#include <cuda_runtime.h>
#include <cuda_bf16.h>
#include <math.h>

#define NN 160
#define EE 256
#define HH 4
#define DD 64
#define ROWS (NN*NN)          // 25600
#define PC 784                // packed projection cols
#define SCALE 0.125f
#define LN_EPS 1e-5f

// column offsets in packed projection
#define C_QIN   0
#define C_KIN   256
#define C_VIN   320
#define C_EGIN  384
#define C_QOUT  392
#define C_KOUT  648
#define C_VOUT  712
#define C_EGOUT 776

typedef unsigned long long u64;

// -------------------- f32x2 packed helpers (sm_10x) ------------------------
__device__ __forceinline__ void fma2(u64 &d, u64 a, u64 b) {
    asm("fma.rn.f32x2 %0, %1, %2, %3;" : "=l"(d) : "l"(a), "l"(b), "l"(d));
}
__device__ __forceinline__ u64 mul2(u64 a, u64 b) {
    u64 r; asm("mul.rn.f32x2 %0, %1, %2;" : "=l"(r) : "l"(a), "l"(b)); return r;
}
__device__ __forceinline__ u64 add2(u64 a, u64 b) {
    u64 r; asm("add.rn.f32x2 %0, %1, %2;" : "=l"(r) : "l"(a), "l"(b)); return r;
}
__device__ __forceinline__ u64 pk2(float x, float y) {
    u64 r;
    asm("mov.b64 %0, {%1, %2};" : "=l"(r) : "r"(__float_as_uint(x)), "r"(__float_as_uint(y)));
    return r;
}
__device__ __forceinline__ void up2(u64 a, float &x, float &y) {
    unsigned lo, hi;
    asm("mov.b64 {%0, %1}, %2;" : "=r"(lo), "=r"(hi) : "l"(a));
    x = __uint_as_float(lo); y = __uint_as_float(hi);
}

// -------------------- scratch ----------------------------------------------
__device__ float g_eln[ROWS * EE];
__device__ float g_proj[ROWS * PC];
__device__ float g_va[ROWS * 512];
__device__ float g_wcat[EE * PC];
__device__ float g_bcat[PC];

// -------------------- block reduce helper (256 threads) --------------------
__device__ __forceinline__ float block_sum256(float v) {
    __shared__ float red[8];
    __shared__ float tot;
    #pragma unroll
    for (int o = 16; o; o >>= 1) v += __shfl_xor_sync(~0u, v, o);
    int wid = threadIdx.x >> 5, lane = threadIdx.x & 31;
    if (lane == 0) red[wid] = v;
    __syncthreads();
    float s = (lane < 8) ? red[lane] : 0.f;
    #pragma unroll
    for (int o = 4; o; o >>= 1) s += __shfl_xor_sync(~0u, s, o);
    if (threadIdx.x == 0) tot = s;
    __syncthreads();
    return tot;
}

// -------------------- LayerNorm --------------------------------------------
__global__ void ln_kernel(const float* __restrict__ e,
                          const float* __restrict__ g,
                          const float* __restrict__ b) {
    int r = blockIdx.x;
    int c = threadIdx.x;
    float x = e[(size_t)r * EE + c];
    float mu = block_sum256(x) * (1.f / EE);
    float dx = x - mu;
    float var = block_sum256(dx * dx) * (1.f / EE);
    g_eln[(size_t)r * EE + c] = dx * rsqrtf(var + LN_EPS) * g[c] + b[c];
}

// -------------------- pack weights (fold SCALE into Q) ----------------------
__global__ void pack_kernel(const float* __restrict__ Wq_in,  const float* __restrict__ bq_in,
                            const float* __restrict__ Wkv_in, const float* __restrict__ bkv_in,
                            const float* __restrict__ Weg_in, const float* __restrict__ beg_in,
                            const float* __restrict__ Wq_out, const float* __restrict__ bq_out,
                            const float* __restrict__ Wkv_out,const float* __restrict__ bkv_out,
                            const float* __restrict__ Weg_out,const float* __restrict__ beg_out) {
    int k = blockIdx.x; // 0..255
    for (int c = threadIdx.x; c < PC; c += blockDim.x) {
        float w, bb;
        if (c < 256)      { w = Wq_in [k*256 +  c      ]*SCALE; bb = bq_in [c      ]*SCALE; }
        else if (c < 384) { w = Wkv_in[k*128 + (c-256) ];       bb = bkv_in[c-256  ]; }
        else if (c < 392) { w = Weg_in[k*8   + (c-384) ];       bb = beg_in[c-384  ]; }
        else if (c < 648) { w = Wq_out[k*256 + (c-392) ]*SCALE; bb = bq_out[c-392  ]*SCALE; }
        else if (c < 776) { w = Wkv_out[k*128+ (c-648) ];       bb = bkv_out[c-648 ]; }
        else              { w = Weg_out[k*8  + (c-776) ];       bb = beg_out[c-776 ]; }
        g_wcat[k*PC + c] = w;
        if (k == 0) g_bcat[c] = bb;
    }
}

// -------------------- SGEMM 128x64x16, 256 threads, f32x2 packed ------------
__global__ __launch_bounds__(256)
void sgemm_bias(const float* __restrict__ A, const float* __restrict__ B,
                const float* __restrict__ bias, float* __restrict__ C,
                int M, int N, int K) {
    const int BM = 128, BN = 64, BK = 16;
    __shared__ float As[BK][BM + 4];
    __shared__ float Bs[BK][BN + 4];
    int tid = threadIdx.x;
    int tr = tid >> 4;      // 0..15
    int tc = tid & 15;      // 0..15
    int bm = blockIdx.y * BM;
    int bn = blockIdx.x * BN;
    // acc pairs along m: accp[mp][n] = (C[2mp][n], C[2mp+1][n])
    u64 accp[4][4];
    #pragma unroll
    for (int mp = 0; mp < 4; mp++)
        #pragma unroll
        for (int n = 0; n < 4; n++) accp[mp][n] = 0ull;

    for (int k0 = 0; k0 < K; k0 += BK) {
        #pragma unroll
        for (int l = 0; l < 2; l++) {
            int i = tid * 2 + l;               // 0..511
            int row = i >> 2;                  // 0..127
            int kq = (i & 3) * 4;              // 0,4,8,12
            float4 v = *(const float4*)(A + (size_t)(bm + row) * K + k0 + kq);
            As[kq + 0][row] = v.x; As[kq + 1][row] = v.y;
            As[kq + 2][row] = v.z; As[kq + 3][row] = v.w;
        }
        {
            int row = tid >> 4;                // 0..15
            int cq = (tid & 15) * 4;           // 0..60
            float4 v = make_float4(0.f, 0.f, 0.f, 0.f);
            if (bn + cq < N)
                v = *(const float4*)(B + (size_t)(k0 + row) * N + bn + cq);
            *(float4*)&Bs[row][cq] = v;
        }
        __syncthreads();
        #pragma unroll
        for (int kk = 0; kk < BK; kk++) {
            const u64* ap = (const u64*)&As[kk][tr * 8];   // 8B aligned (tr*8 even)
            u64 a0 = ap[0], a1 = ap[1], a2 = ap[2], a3 = ap[3];
            float4 bv = *(const float4*)&Bs[kk][tc * 4];
            u64 bd0 = pk2(bv.x, bv.x), bd1 = pk2(bv.y, bv.y);
            u64 bd2 = pk2(bv.z, bv.z), bd3 = pk2(bv.w, bv.w);
            fma2(accp[0][0], a0, bd0); fma2(accp[0][1], a0, bd1);
            fma2(accp[0][2], a0, bd2); fma2(accp[0][3], a0, bd3);
            fma2(accp[1][0], a1, bd0); fma2(accp[1][1], a1, bd1);
            fma2(accp[1][2], a1, bd2); fma2(accp[1][3], a1, bd3);
            fma2(accp[2][0], a2, bd0); fma2(accp[2][1], a2, bd1);
            fma2(accp[2][2], a2, bd2); fma2(accp[2][3], a2, bd3);
            fma2(accp[3][0], a3, bd0); fma2(accp[3][1], a3, bd1);
            fma2(accp[3][2], a3, bd2); fma2(accp[3][3], a3, bd3);
        }
        __syncthreads();
    }
    #pragma unroll
    for (int mp = 0; mp < 4; mp++) {
        int row0 = bm + tr * 8 + 2 * mp;
        #pragma unroll
        for (int n = 0; n < 4; n++) {
            int col = bn + tc * 4 + n;
            if (col < N) {
                float x0, x1; up2(accp[mp][n], x0, x1);
                float bz = bias[col];
                C[(size_t)row0 * N + col]       = x0 + bz;
                C[(size_t)(row0 + 1) * N + col] = x1 + bz;
            }
        }
    }
}

// -------------------- flash-style triangle attention ------------------------
// block = (j, ic, br); 128 threads; thread owns row (i = ic*32 + tid>>2, h = tid&3)
// Q row and AV accumulator register-resident (f32x2 packed); K/V broadcast LDS.64.
#define EGP 12
#define SM_KS 0
#define SM_VS (160*64)
#define SM_EG (2*160*64)
#define SM_TOT ((2*160*64 + 8*32*EGP) * 4)   // 94208 bytes

__global__ __launch_bounds__(128, 2)
void attn_flash(const float* __restrict__ proj, const float* __restrict__ mask,
                float* __restrict__ va) {
    extern __shared__ float sm[];
    float* Ks  = sm + SM_KS;
    float* Vs  = sm + SM_VS;
    float* egs = sm + SM_EG;

    const int j  = blockIdx.x;
    const int ic = blockIdx.y;
    const int br = blockIdx.z;            // 0 = in, 1 = out
    const int tid = threadIdx.x;
    const int il = tid >> 2, h = tid & 3;
    const int i  = ic * 32 + il;
    const int KVB = br ? C_KOUT : C_KIN;
    const int QB  = br ? C_QOUT : C_QIN;
    const int EGB = br ? C_EGOUT : C_EGIN;

    // stage K/V for this j
    for (int idx = tid; idx < 160 * 32; idx += 128) {
        int k = idx >> 5, c = idx & 31;
        int row = br ? (k * NN + j) : (j * NN + k);
        float4 v = *(const float4*)(proj + (size_t)row * PC + KVB + c * 4);
        if (c < 16) *(float4*)&Ks[k * 64 + c * 4] = v;
        else        *(float4*)&Vs[k * 64 + (c - 16) * 4] = v;
    }

    // Q row into registers, packed along d
    u64 q2[32];
    {
        const float* qp = proj + (size_t)(i * NN + j) * PC + QB + h;
        #pragma unroll
        for (int u = 0; u < 32; u++)
            q2[u] = pk2(qp[(2 * u) * 4], qp[(2 * u + 1) * 4]);
    }
    u64 acc[32];
    #pragma unroll
    for (int u = 0; u < 32; u++) acc[u] = 0ull;
    float mx = -1e30f, s = 0.f;

    __syncthreads();

    for (int t = 0; t < 20; t++) {
        // stage EG/mask tile: 8 k's x 32 i's x (8 eg + 1 mask), pitch 12
        for (int sg = tid; sg < 256; sg += 128) {
            int kk = sg >> 5, ii = sg & 31;
            int i2 = ic * 32 + ii, k = t * 8 + kk;
            int row = br ? (k * NN + i2) : (i2 * NN + k);
            const float* p = proj + (size_t)row * PC + EGB;
            float* d = &egs[(kk * 32 + ii) * EGP];
            *(float4*)d       = *(const float4*)p;
            *(float4*)(d + 4) = *(const float4*)(p + 4);
            d[8] = mask[row];
        }
        __syncthreads();

        float lg[8], gg[8];
        #pragma unroll
        for (int kk = 0; kk < 8; kk++) {
            const u64* kp = (const u64*)&Ks[(t * 8 + kk) * 64];
            u64 da = 0ull, db = 0ull, dc = 0ull, dd = 0ull;
            #pragma unroll
            for (int u = 0; u < 8; u++) {
                fma2(da, q2[u],      kp[u]);
                fma2(db, q2[u + 8],  kp[u + 8]);
                fma2(dc, q2[u + 16], kp[u + 16]);
                fma2(dd, q2[u + 24], kp[u + 24]);
            }
            u64 dt = add2(add2(da, db), add2(dc, dd));
            float a0, a1; up2(dt, a0, a1);
            const float* ep = &egs[(kk * 32 + il) * EGP];
            float m = ep[8];
            lg[kk] = a0 + a1 + ep[h] + m;
            gg[kk] = ep[4 + h] + m;
        }

        float tm = lg[0];
        #pragma unroll
        for (int kk = 1; kk < 8; kk++) tm = fmaxf(tm, lg[kk]);
        float nm = fmaxf(mx, tm);
        if (nm > mx) {
            float f = __expf(mx - nm);
            mx = nm; s *= f;
            u64 pf = pk2(f, f);
            #pragma unroll
            for (int u = 0; u < 32; u++) acc[u] = mul2(acc[u], pf);
        }
        #pragma unroll
        for (int kk = 0; kk < 8; kk++) {
            float p = __expf(lg[kk] - mx);
            s += p;
            float gate = __fdividef(1.f, 1.f + __expf(-gg[kk]));
            float w = p * gate;
            u64 pw = pk2(w, w);
            const u64* vp = (const u64*)&Vs[(t * 8 + kk) * 64];
            #pragma unroll
            for (int u = 0; u < 32; u++) fma2(acc[u], pw, vp[u]);
        }
        __syncthreads();
    }

    float rinv = __fdividef(1.f, s);
    float* op = va + (size_t)(i * NN + j) * 512 + (br ? 4 : 0) + h;
    #pragma unroll
    for (int u = 0; u < 32; u++) {
        float a0, a1; up2(acc[u], a0, a1);
        op[(2 * u) * 8]     = a0 * rinv;
        op[(2 * u + 1) * 8] = a1 * rinv;
    }
}

// -------------------- launch -----------------------------------------------
extern "C" void kernel_launch(void* const* d_in, const int* in_sizes, int n_in,
                              void* d_out, int out_size) {
    const float* e       = (const float*)d_in[0];
    const float* mask    = (const float*)d_in[1];
    const float* ln_g    = (const float*)d_in[2];
    const float* ln_b    = (const float*)d_in[3];
    const float* Wq_in   = (const float*)d_in[4];
    const float* bq_in   = (const float*)d_in[5];
    const float* Wkv_in  = (const float*)d_in[6];
    const float* bkv_in  = (const float*)d_in[7];
    const float* Weg_in  = (const float*)d_in[8];
    const float* beg_in  = (const float*)d_in[9];
    const float* Wq_out  = (const float*)d_in[10];
    const float* bq_out  = (const float*)d_in[11];
    const float* Wkv_out = (const float*)d_in[12];
    const float* bkv_out = (const float*)d_in[13];
    const float* Weg_out = (const float*)d_in[14];
    const float* beg_out = (const float*)d_in[15];
    const float* Wo      = (const float*)d_in[16];
    const float* bo      = (const float*)d_in[17];
    float* out = (float*)d_out;

    float *p_eln, *p_proj, *p_va, *p_wcat, *p_bcat;
    cudaGetSymbolAddress((void**)&p_eln,  g_eln);
    cudaGetSymbolAddress((void**)&p_proj, g_proj);
    cudaGetSymbolAddress((void**)&p_va,   g_va);
    cudaGetSymbolAddress((void**)&p_wcat, g_wcat);
    cudaGetSymbolAddress((void**)&p_bcat, g_bcat);

    cudaFuncSetAttribute(attn_flash, cudaFuncAttributeMaxDynamicSharedMemorySize, SM_TOT);

    // 1. LayerNorm
    ln_kernel<<<ROWS, 256>>>(e, ln_g, ln_b);
    // 2. pack weights
    pack_kernel<<<EE, 256>>>(Wq_in, bq_in, Wkv_in, bkv_in, Weg_in, beg_in,
                             Wq_out, bq_out, Wkv_out, bkv_out, Weg_out, beg_out);
    // 3. all projections in one GEMM: [25600,256] x [256,784]
    sgemm_bias<<<dim3((PC + 63) / 64, ROWS / 128), 256>>>(p_eln, p_wcat, p_bcat, p_proj,
                                                          ROWS, PC, EE);
    // 4. fused flash attention, both branches in one launch
    attn_flash<<<dim3(NN, NN / 32, 2), 128, SM_TOT>>>(p_proj, mask, p_va);
    // 5. output projection: [25600,512] x [512,256] -> d_out
    sgemm_bias<<<dim3(256 / 64, ROWS / 128), 256>>>(p_va, Wo, bo, out,
                                                    ROWS, EE, 2 * EE);
}